// round 7
// baseline (speedup 1.0000x reference)
#include <cuda_runtime.h>
#include <cuda_bf16.h>

// warp3D trilinear backward-warp, two-phase, x-pair + channel packed gathers.
//  1) pack_kernel: g4[v] = (c0[v], c1[v], c0[v+1], c1[v+1])  (220MB scratch,
//     coalesced streaming pass). Each corner-PAIR along x + both channels is
//     one aligned 16B element.
//  2) warp3d_quad: per output point only 4 x LDG.E.128 gathers (one per
//     (z,y) corner row) instead of 16 x 4B naive / 8 x 8B previous. ncu showed
//     L1tex wavefronts are the binding pipe; unique-line touches ~halve.
// Math matches reference (clamp-order + clamped-x1 weights). When x1==x0
// (border clamp) the packed hi slot is the wrong voxel, so the x-weights fold
// to (1, 0) -- algebraically identical to dx+ex = 1 on the same voxel.

#define BB 2
#define CC 2
#define DD 160
#define HH 192
#define WW 224

static constexpr int HW  = HH * WW;          // 43008
static constexpr int DHW = DD * HW;          // 6,881,280
static constexpr int NPAIR = BB * DHW;       // 13,762,560 voxels

// 220 MB packed scratch: (c0[v], c1[v], c0[v+1], c1[v+1])
__device__ float4 g4[NPAIR];

// ---------------- Phase 1: planar -> packed quad ----------------
static constexpr int PK_THREADS = 256;
static constexpr int PK_TOTAL   = NPAIR / 4;           // 3,440,640 (4 voxels/thread)

__global__ __launch_bounds__(PK_THREADS)
void pack_kernel(const float* __restrict__ I)
{
    int i = blockIdx.x * PK_THREADS + threadIdx.x;
    if (i >= PK_TOTAL) return;
    int v = i << 2;                    // first voxel (global, batch-major)
    int b = (v >= DHW) ? 1 : 0;
    int s = v - b * DHW;

    const float* __restrict__ I0 = I + (size_t)b * CC * DHW;
    const float* __restrict__ I1 = I0 + DHW;

    const float4 a = *(const float4*)(I0 + s);   // c0[s..s+3]
    const float4 c = *(const float4*)(I1 + s);   // c1[s..s+3]
    // +1 neighbor of the 4th voxel; value only ever used with weight 0 when
    // it crosses a row/batch boundary, but must be in-bounds.
    int sn = (s + 4 < DHW) ? s + 4 : s + 3;
    float an = I0[sn];
    float cn = I1[sn];

    float4* dst = g4 + v;
    dst[0] = make_float4(a.x, c.x, a.y, c.y);
    dst[1] = make_float4(a.y, c.y, a.z, c.z);
    dst[2] = make_float4(a.z, c.z, a.w, c.w);
    dst[3] = make_float4(a.w, c.w, an, cn);
}

// ---------------- Phase 2: gather/interpolate ----------------
// Block = one x-row (224 threads); blockIdx = (h, d, b). No div/mod.
__global__ __launch_bounds__(WW)
void warp3d_quad(const float* __restrict__ flow,
                 float* __restrict__ out)
{
    const int w = threadIdx.x;
    const int h = blockIdx.x;
    const int d = blockIdx.y;
    const int b = blockIdx.z;

    const int s = d * HW + h * WW + w;

    const float* __restrict__ fb = flow + (size_t)b * 3 * DHW;
    float x = fb[s]           + (float)w;
    float y = fb[s + DHW]     + (float)h;
    float z = fb[s + 2 * DHW] + (float)d;

    int x0r = (int)floorf(x);
    int y0r = (int)floorf(y);
    int z0r = (int)floorf(z);

    int x1 = min(max(x0r + 1, 0), WW - 1);
    int y1 = min(max(y0r + 1, 0), HH - 1);
    int z1 = min(max(z0r + 1, 0), DD - 1);
    int x0 = min(max(x0r, 0), WW - 1);
    int y0 = min(max(y0r, 0), HH - 1);
    int z0 = min(max(z0r, 0), DD - 1);

    // Weights from CLAMPED upper corner (matches reference)
    float dx = (float)x1 - x;
    float dy = (float)y1 - y;
    float dz = (float)z1 - z;
    float ex = 1.0f - dx;
    float ey = 1.0f - dy;
    float ez = 1.0f - dz;

    // x-pair weights: packed hi slot is voxel x0+1, valid iff x1 == x0+1.
    // Otherwise (border clamp, x1==x0) fold dx+ex = 1 onto the lo voxel.
    bool xsame = (x1 == x0);
    float wl = xsame ? 1.0f : dx;
    float wh = xsame ? 0.0f : ex;

    const float4* __restrict__ P = g4 + (size_t)b * DHW;

    int r00 = z0 * HW + y0 * WW + x0;
    int r01 = z0 * HW + y1 * WW + x0;
    int r10 = z1 * HW + y0 * WW + x0;
    int r11 = z1 * HW + y1 * WW + x0;

    float4 v00 = __ldg(P + r00);   // (c0[x0], c1[x0], c0[x0+1], c1[x0+1]) @ (z0,y0)
    float4 v01 = __ldg(P + r01);   // @ (z0,y1)
    float4 v10 = __ldg(P + r10);   // @ (z1,y0)
    float4 v11 = __ldg(P + r11);   // @ (z1,y1)

    // x-combine per row, per channel
    float s00c0 = fmaf(wh, v00.z, wl * v00.x);
    float s00c1 = fmaf(wh, v00.w, wl * v00.y);
    float s01c0 = fmaf(wh, v01.z, wl * v01.x);
    float s01c1 = fmaf(wh, v01.w, wl * v01.y);
    float s10c0 = fmaf(wh, v10.z, wl * v10.x);
    float s10c1 = fmaf(wh, v10.w, wl * v10.y);
    float s11c0 = fmaf(wh, v11.z, wl * v11.x);
    float s11c1 = fmaf(wh, v11.w, wl * v11.y);

    float w00 = dz * dy;
    float w01 = dz * ey;
    float w10 = ez * dy;
    float w11 = ez * ey;

    float acc0 = w00 * s00c0;
    acc0 = fmaf(w01, s01c0, acc0);
    acc0 = fmaf(w10, s10c0, acc0);
    acc0 = fmaf(w11, s11c0, acc0);

    float acc1 = w00 * s00c1;
    acc1 = fmaf(w01, s01c1, acc1);
    acc1 = fmaf(w10, s10c1, acc1);
    acc1 = fmaf(w11, s11c1, acc1);

    float* __restrict__ ob = out + (size_t)b * CC * DHW;
    ob[s]       = acc0;
    ob[s + DHW] = acc1;
}

extern "C" void kernel_launch(void* const* d_in, const int* in_sizes, int n_in,
                              void* d_out, int out_size)
{
    const float* I    = (const float*)d_in[0];
    const float* flow = (const float*)d_in[1];
    float* out        = (float*)d_out;

    pack_kernel<<<(PK_TOTAL + PK_THREADS - 1) / PK_THREADS, PK_THREADS>>>(I);

    dim3 grid(HH, DD, BB);             // block = one x-row of 224 threads
    warp3d_quad<<<grid, WW>>>(flow, out);
}

// round 9
// speedup vs baseline: 1.2648x; 1.2648x over previous
#include <cuda_runtime.h>
#include <cuda_bf16.h>
#include <cuda_fp16.h>

// warp3D trilinear backward-warp, two-phase, fp16 packed-gather version.
//  1) pack_kernel: g8[v] = { half2(c0[v],c1[v]), half2(c0[v+1],c1[v+1]) }
//     -> 8 bytes per voxel covering BOTH channels at x and x+1. 110 MB scratch,
//     coalesced streaming pass.
//  2) warp3d_h2: per output point only 4 x LDG.64 gathers (one per (z,y)
//     corner row), 32 B/point total -- HALF the gather bytes & L1 wavefronts
//     of every fp32 variant (which all moved 64 B/point and converged at
//     ~165us with L1tex binding).
// Weights are computed in fp32 exactly as the reference (clamp-order +
// clamped-x1); only the I samples are fp16-rounded (~2e-4 rel err, tolerance
// is 1e-3). When x1==x0 (border) the x-weights fold to (1,0), algebraically
// identical to dx+ex=1 on the clamped voxel.

#define BB 2
#define CC 2
#define DD 160
#define HH 192
#define WW 224

static constexpr int HW  = HH * WW;          // 43008
static constexpr int DHW = DD * HW;          // 6,881,280
static constexpr int NVOX = BB * DHW;        // 13,762,560 voxels

// 110 MB packed scratch: per voxel, (c0,c1)@x as half2 and (c0,c1)@x+1 as half2
__device__ uint2 g8[NVOX];

__device__ __forceinline__ unsigned h2_bits(__half2 v)
{
    return *reinterpret_cast<unsigned*>(&v);
}

__device__ __forceinline__ float2 h2f(unsigned u)
{
    __half2 v = *reinterpret_cast<__half2*>(&u);
    return __half22float2(v);
}

// ---------------- Phase 1: planar fp32 -> packed fp16 quad ----------------
static constexpr int PK_THREADS = 256;
static constexpr int PK_TOTAL   = NVOX / 4;            // 3,440,640 (4 voxels/thread)

__global__ __launch_bounds__(PK_THREADS)
void pack_kernel(const float* __restrict__ I)
{
    int i = blockIdx.x * PK_THREADS + threadIdx.x;
    if (i >= PK_TOTAL) return;
    int v = i << 2;                    // first voxel (global, batch-major)
    int b = (v >= DHW) ? 1 : 0;
    int s = v - b * DHW;

    const float* __restrict__ I0 = I + (size_t)b * CC * DHW;
    const float* __restrict__ I1 = I0 + DHW;

    const float4 a = *(const float4*)(I0 + s);   // c0[s..s+3]
    const float4 c = *(const float4*)(I1 + s);   // c1[s..s+3]
    // neighbor of the 4th voxel; used with weight 0 at borders but must be
    // in-bounds and finite.
    int sn = (s + 4 < DHW) ? s + 4 : s + 3;
    float an = I0[sn];
    float cn = I1[sn];

    unsigned p0 = h2_bits(__floats2half2_rn(a.x, c.x));
    unsigned p1 = h2_bits(__floats2half2_rn(a.y, c.y));
    unsigned p2 = h2_bits(__floats2half2_rn(a.z, c.z));
    unsigned p3 = h2_bits(__floats2half2_rn(a.w, c.w));
    unsigned p4 = h2_bits(__floats2half2_rn(an,  cn));

    uint2* dst = g8 + v;
    dst[0] = make_uint2(p0, p1);
    dst[1] = make_uint2(p1, p2);
    dst[2] = make_uint2(p2, p3);
    dst[3] = make_uint2(p3, p4);
}

// ---------------- Phase 2: gather/interpolate ----------------
// Block = one x-row (224 threads); blockIdx = (h, d, b). No div/mod.
__global__ __launch_bounds__(WW)
void warp3d_h2(const float* __restrict__ flow,
               float* __restrict__ out)
{
    const int w = threadIdx.x;
    const int h = blockIdx.x;
    const int d = blockIdx.y;
    const int b = blockIdx.z;

    const int s = d * HW + h * WW + w;

    const float* __restrict__ fb = flow + (size_t)b * 3 * DHW;
    float x = fb[s]           + (float)w;
    float y = fb[s + DHW]     + (float)h;
    float z = fb[s + 2 * DHW] + (float)d;

    int x0r = (int)floorf(x);
    int y0r = (int)floorf(y);
    int z0r = (int)floorf(z);

    int x1 = min(max(x0r + 1, 0), WW - 1);
    int y1 = min(max(y0r + 1, 0), HH - 1);
    int z1 = min(max(z0r + 1, 0), DD - 1);
    int x0 = min(max(x0r, 0), WW - 1);
    int y0 = min(max(y0r, 0), HH - 1);
    int z0 = min(max(z0r, 0), DD - 1);

    // Weights from CLAMPED upper corner (matches reference)
    float dx = (float)x1 - x;
    float dy = (float)y1 - y;
    float dz = (float)z1 - z;
    float ex = 1.0f - dx;
    float ey = 1.0f - dy;
    float ez = 1.0f - dz;

    // x-pair weights: packed hi slot is voxel x0+1, valid iff x1 == x0+1.
    bool xsame = (x1 == x0);
    float wl = xsame ? 1.0f : dx;
    float wh = xsame ? 0.0f : ex;

    const uint2* __restrict__ P = g8 + (size_t)b * DHW;

    int r00 = z0 * HW + y0 * WW + x0;
    int r01 = z0 * HW + y1 * WW + x0;
    int r10 = z1 * HW + y0 * WW + x0;
    int r11 = z1 * HW + y1 * WW + x0;

    uint2 q00 = __ldg(P + r00);   // @(z0,y0): lo=(c0,c1)@x0, hi=@x0+1
    uint2 q01 = __ldg(P + r01);   // @(z0,y1)
    uint2 q10 = __ldg(P + r10);   // @(z1,y0)
    uint2 q11 = __ldg(P + r11);   // @(z1,y1)

    float2 l00 = h2f(q00.x), h00 = h2f(q00.y);
    float2 l01 = h2f(q01.x), h01 = h2f(q01.y);
    float2 l10 = h2f(q10.x), h10 = h2f(q10.y);
    float2 l11 = h2f(q11.x), h11 = h2f(q11.y);

    // x-combine per row, per channel (fp32)
    float s00c0 = fmaf(wh, h00.x, wl * l00.x);
    float s00c1 = fmaf(wh, h00.y, wl * l00.y);
    float s01c0 = fmaf(wh, h01.x, wl * l01.x);
    float s01c1 = fmaf(wh, h01.y, wl * l01.y);
    float s10c0 = fmaf(wh, h10.x, wl * l10.x);
    float s10c1 = fmaf(wh, h10.y, wl * l10.y);
    float s11c0 = fmaf(wh, h11.x, wl * l11.x);
    float s11c1 = fmaf(wh, h11.y, wl * l11.y);

    float w00 = dz * dy;
    float w01 = dz * ey;
    float w10 = ez * dy;
    float w11 = ez * ey;

    float acc0 = w00 * s00c0;
    acc0 = fmaf(w01, s01c0, acc0);
    acc0 = fmaf(w10, s10c0, acc0);
    acc0 = fmaf(w11, s11c0, acc0);

    float acc1 = w00 * s00c1;
    acc1 = fmaf(w01, s01c1, acc1);
    acc1 = fmaf(w10, s10c1, acc1);
    acc1 = fmaf(w11, s11c1, acc1);

    float* __restrict__ ob = out + (size_t)b * CC * DHW;
    ob[s]       = acc0;
    ob[s + DHW] = acc1;
}

extern "C" void kernel_launch(void* const* d_in, const int* in_sizes, int n_in,
                              void* d_out, int out_size)
{
    const float* I    = (const float*)d_in[0];
    const float* flow = (const float*)d_in[1];
    float* out        = (float*)d_out;

    pack_kernel<<<(PK_TOTAL + PK_THREADS - 1) / PK_THREADS, PK_THREADS>>>(I);

    dim3 grid(HH, DD, BB);             // block = one x-row of 224 threads
    warp3d_h2<<<grid, WW>>>(flow, out);
}

// round 11
// speedup vs baseline: 1.3230x; 1.0460x over previous
#include <cuda_runtime.h>
#include <cuda_bf16.h>
#include <cuda_fp16.h>

// warp3D trilinear backward-warp, two-phase, fp16 z+x corner-packed gathers.
//  Scratch element g16[b][z][y][x] (16B, uint4) holds fp16 (c0,c1) at the four
//  corners {z,z+1} x {x,x+1}. A whole trilinear sample then needs only TWO
//  LDG.128 gathers (rows y0 and y1): x- and z-lerp come out of one element.
//  ncu showed L1 gather wavefronts bind (2.3/point with 4 gathers); this
//  halves gather instructions -> ~1.3 wavefronts/point.
// Weights fp32, exactly the reference (clamp-order + clamped-upper-corner).
// At borders (x1==x0 / z1==z0) the axis weights fold to (1,0): algebraically
// identical to dx+ex=1 (dz+ez=1) applied to the clamped voxel.
// fp16 sample rounding -> rel_err ~2e-4 (validated R9), tolerance 1e-3.

#define BB 2
#define CC 2
#define DD 160
#define HH 192
#define WW 224

static constexpr int HW  = HH * WW;          // 43008
static constexpr int DHW = DD * HW;          // 6,881,280
static constexpr int NVOX = BB * DHW;        // 13,762,560 voxels

// 220 MB packed scratch
__device__ uint4 g16[NVOX];

__device__ __forceinline__ unsigned h2_bits(__half2 v)
{
    return *reinterpret_cast<unsigned*>(&v);
}

__device__ __forceinline__ float2 h2f(unsigned u)
{
    __half2 v = *reinterpret_cast<__half2*>(&u);
    return __half22float2(v);
}

// ---------------- Phase 1: planar fp32 -> packed corner quads ----------------
// Thread handles 4 consecutive x of one (b,z,y) row; reads rows z and z+1.
static constexpr int PK_THREADS = 256;
static constexpr int PK_TOTAL   = NVOX / 4;            // 3,440,640

__global__ __launch_bounds__(PK_THREADS)
void pack_kernel(const float* __restrict__ I)
{
    int i = blockIdx.x * PK_THREADS + threadIdx.x;
    if (i >= PK_TOTAL) return;
    int v = i << 2;                      // first voxel (global, batch-major)
    int b = (v >= DHW) ? 1 : 0;
    int s = v - b * DHW;
    int z = s / HW;
    int r = s - z * HW;
    int y = r / WW;
    int x = r - y * WW;                  // multiple of 4

    const float* __restrict__ base = I + (size_t)b * CC * DHW;  // c0 plane
    int zp = (z + 1 < DD) ? z + 1 : z;   // clamped z+1 row (dup at border, weight 0)
    int sB = zp * HW + y * WW + x;

    const float4 c0A = *(const float4*)(base + s);
    const float4 c1A = *(const float4*)(base + DHW + s);
    const float4 c0B = *(const float4*)(base + sB);
    const float4 c1B = *(const float4*)(base + DHW + sB);

    int xn  = (x + 4 < WW) ? x + 4 : WW - 1;     // x+1 neighbor of 4th voxel
    int snA = z * HW + y * WW + xn;
    int snB = zp * HW + y * WW + xn;
    float n0A = base[snA],        n1A = base[DHW + snA];
    float n0B = base[snB],        n1B = base[DHW + snB];

    // per-x fp16 pairs, rows A (z) and B (z+1)
    unsigned a0 = h2_bits(__floats2half2_rn(c0A.x, c1A.x));
    unsigned a1 = h2_bits(__floats2half2_rn(c0A.y, c1A.y));
    unsigned a2 = h2_bits(__floats2half2_rn(c0A.z, c1A.z));
    unsigned a3 = h2_bits(__floats2half2_rn(c0A.w, c1A.w));
    unsigned a4 = h2_bits(__floats2half2_rn(n0A,   n1A));
    unsigned b0 = h2_bits(__floats2half2_rn(c0B.x, c1B.x));
    unsigned b1 = h2_bits(__floats2half2_rn(c0B.y, c1B.y));
    unsigned b2 = h2_bits(__floats2half2_rn(c0B.z, c1B.z));
    unsigned b3 = h2_bits(__floats2half2_rn(c0B.w, c1B.w));
    unsigned b4 = h2_bits(__floats2half2_rn(n0B,   n1B));

    uint4* dst = g16 + v;
    dst[0] = make_uint4(a0, a1, b0, b1);   // (z,x),(z,x+1),(z+1,x),(z+1,x+1)
    dst[1] = make_uint4(a1, a2, b1, b2);
    dst[2] = make_uint4(a2, a3, b2, b3);
    dst[3] = make_uint4(a3, a4, b3, b4);
}

// ---------------- Phase 2: gather/interpolate, 2 points/thread ----------------
// Block = one x-row (224 threads); blockIdx = (h-pair, d, b). No div/mod.
static constexpr int HH2 = HH / 2;       // 96

__device__ __forceinline__ void sample_one(
    const float* __restrict__ fb, const uint4* __restrict__ P,
    float* __restrict__ ob, int w, int h, int d)
{
    const int s = d * HW + h * WW + w;

    float x = fb[s]           + (float)w;
    float y = fb[s + DHW]     + (float)h;
    float z = fb[s + 2 * DHW] + (float)d;

    int x0r = (int)floorf(x);
    int y0r = (int)floorf(y);
    int z0r = (int)floorf(z);

    int x1 = min(max(x0r + 1, 0), WW - 1);
    int y1 = min(max(y0r + 1, 0), HH - 1);
    int z1 = min(max(z0r + 1, 0), DD - 1);
    int x0 = min(max(x0r, 0), WW - 1);
    int y0 = min(max(y0r, 0), HH - 1);
    int z0 = min(max(z0r, 0), DD - 1);

    // Reference weights from CLAMPED upper corner
    float dx = (float)x1 - x;
    float dy = (float)y1 - y;
    float dz = (float)z1 - z;
    float ex = 1.0f - dx;
    float ey = 1.0f - dy;
    float ez = 1.0f - dz;

    // fold to (1,0) at border clamps (hi slot holds a duplicate there)
    bool xsame = (x1 == x0);
    float wxl = xsame ? 1.0f : dx;
    float wxh = xsame ? 0.0f : ex;
    bool zsame = (z1 == z0);
    float wzl = zsame ? 1.0f : dz;
    float wzh = zsame ? 0.0f : ez;

    uint4 q0 = __ldg(P + z0 * HW + y0 * WW + x0);  // row y0: 4 corners
    uint4 q1 = __ldg(P + z0 * HW + y1 * WW + x0);  // row y1

    // x-lerp then z-lerp within each element, per channel (float2 = both ch)
    float2 e00 = h2f(q0.x), e01 = h2f(q0.y), e02 = h2f(q0.z), e03 = h2f(q0.w);
    float2 e10 = h2f(q1.x), e11 = h2f(q1.y), e12 = h2f(q1.z), e13 = h2f(q1.w);

    float r0c0 = wzl * fmaf(wxh, e01.x, wxl * e00.x)
               + wzh * fmaf(wxh, e03.x, wxl * e02.x);
    float r0c1 = wzl * fmaf(wxh, e01.y, wxl * e00.y)
               + wzh * fmaf(wxh, e03.y, wxl * e02.y);
    float r1c0 = wzl * fmaf(wxh, e11.x, wxl * e10.x)
               + wzh * fmaf(wxh, e13.x, wxl * e12.x);
    float r1c1 = wzl * fmaf(wxh, e11.y, wxl * e10.y)
               + wzh * fmaf(wxh, e13.y, wxl * e12.y);

    float acc0 = fmaf(dy, r0c0, ey * r1c0);
    float acc1 = fmaf(dy, r0c1, ey * r1c1);

    ob[s]       = acc0;
    ob[s + DHW] = acc1;
}

__global__ __launch_bounds__(WW)
void warp3d_zx(const float* __restrict__ flow,
               float* __restrict__ out)
{
    const int w = threadIdx.x;
    const int h = blockIdx.x;            // 0..95
    const int d = blockIdx.y;
    const int b = blockIdx.z;

    const float* __restrict__ fb = flow + (size_t)b * 3 * DHW;
    const uint4* __restrict__ P  = g16 + (size_t)b * DHW;
    float* __restrict__ ob       = out + (size_t)b * CC * DHW;

    sample_one(fb, P, ob, w, h,       d);
    sample_one(fb, P, ob, w, h + HH2, d);
}

extern "C" void kernel_launch(void* const* d_in, const int* in_sizes, int n_in,
                              void* d_out, int out_size)
{
    const float* I    = (const float*)d_in[0];
    const float* flow = (const float*)d_in[1];
    float* out        = (float*)d_out;

    pack_kernel<<<(PK_TOTAL + PK_THREADS - 1) / PK_THREADS, PK_THREADS>>>(I);

    dim3 grid(HH2, DD, BB);              // 96 x 160 x 2, 224 threads
    warp3d_zx<<<grid, WW>>>(flow, out);
}